// round 1
// baseline (speedup 1.0000x reference)
#include <cuda_runtime.h>

// KinematicDOFs: backbone prefix-product of 16384 affine transforms +
// 16384 independent 15-long side chains, output = scattered translations.
//
// inputs (metadata order):
//  0 dofs          float32 [4*(NATM-1)]
//  1 full_dofs     float32 [NATM*9]    (all zeros; unused)
//  2 node_idx      int32               (structural; unused — repeat(1..NATM-1,4))
//  3 dof_idx       int32               (structural; unused — tile(0..3))
//  4 doftype       int32 [NATM]        (0=identity,1=jump,2=bond)
//  5 gen0_nodes    int32               (0..16384; unused, structural)
//  6 gen1_nodes    int32               (16385..NATM-1 reshaped; unused, structural)
//  7 gen1_parents  int32 [16384]       (=1..16384)
//  8 kin_id        int32 [NATM]        (random permutation — used for scatter)
// output: float32 [1, NATM-1, 3]

#define B_CHAIN 16384
#define S_SIDE  15
#define TPB     256
#define NBLK    (B_CHAIN / TPB)   // 64

// scratch (no cudaMalloc allowed)
__device__ float g_local[12 * B_CHAIN];   // SoA: component k at g_local[k*B_CHAIN + e]
__device__ float g_agg[NBLK * 12];        // per-block inclusive totals
__device__ float g_seed[NBLK * 12];       // exclusive prefix of block totals

// c = a (then) b, i.e. matrix product a @ b for affine 3x4 (row-major, col 3 = translation)
__device__ __forceinline__ void affmul(const float* a, const float* b, float* c)
{
#pragma unroll
    for (int i = 0; i < 3; ++i) {
        float a0 = a[i*4+0], a1 = a[i*4+1], a2 = a[i*4+2], a3 = a[i*4+3];
        c[i*4+0] = a0*b[0] + a1*b[4] + a2*b[8];
        c[i*4+1] = a0*b[1] + a1*b[5] + a2*b[9];
        c[i*4+2] = a0*b[2] + a1*b[6] + a2*b[10];
        c[i*4+3] = a0*b[3] + a1*b[7] + a2*b[11] + a3;
    }
}

// ht_bond = Rx(a) @ Rz(b) @ T(d,0,0) @ Rx(c)   (closed form)
__device__ __forceinline__ void bond_ht(float a, float b, float d, float c, float* m)
{
    float sa, ca, sb, cb, sc, cc;
    sincosf(a, &sa, &ca);
    sincosf(b, &sb, &cb);
    sincosf(c, &sc, &cc);
    m[0] = cb;      m[1] = -sb*cc;           m[2] =  sb*sc;           m[3]  = d*cb;
    m[4] = ca*sb;   m[5] = ca*cb*cc - sa*sc; m[6] = -ca*cb*sc - sa*cc; m[7] = ca*d*sb;
    m[8] = sa*sb;   m[9] = sa*cb*cc + ca*sc; m[10]= -sa*cb*sc + ca*cc; m[11]= sa*d*sb;
}

__device__ __forceinline__ void make_ht(int dt, float4 d, float* m)
{
    if (dt == 2) {
        bond_ht(d.x, d.y, d.z, d.w, m);
    } else if (dt == 1) {
        // jump with f4=f5=0 (only dof_idx 0..3 ever set): T(f0,f1,f2) @ Rx(f3)
        float s3, c3; sincosf(d.w, &s3, &c3);
        m[0]=1.f; m[1]=0.f; m[2]=0.f;  m[3]=d.x;
        m[4]=0.f; m[5]=c3;  m[6]=-s3;  m[7]=d.y;
        m[8]=0.f; m[9]=s3;  m[10]=c3;  m[11]=d.z;
    } else {
        m[0]=1.f; m[1]=0.f; m[2]=0.f;  m[3]=0.f;
        m[4]=0.f; m[5]=1.f; m[6]=0.f;  m[7]=0.f;
        m[8]=0.f; m[9]=0.f; m[10]=1.f; m[11]=0.f;
    }
}

// ---------------------------------------------------------------------------
// K1: per-block inclusive scan of backbone elements (atoms 1..16384).
// ---------------------------------------------------------------------------
__global__ void __launch_bounds__(TPB)
k_scan1(const float* __restrict__ dofs, const int* __restrict__ doftype)
{
    const int e    = blockIdx.x * TPB + threadIdx.x;  // 0..16383, atom = e+1
    const int atom = e + 1;
    const int lane = threadIdx.x & 31;
    const int warp = threadIdx.x >> 5;

    float4 d = reinterpret_cast<const float4*>(dofs)[e];
    float m[12];
    make_ht(doftype[atom], d, m);

    // warp inclusive scan (Hillis-Steele), prefix = earlier @ current
#pragma unroll
    for (int dlt = 1; dlt < 32; dlt <<= 1) {
        float o[12];
#pragma unroll
        for (int k = 0; k < 12; ++k) o[k] = __shfl_up_sync(0xffffffffu, m[k], dlt);
        if (lane >= dlt) {
            float t[12]; affmul(o, m, t);
#pragma unroll
            for (int k = 0; k < 12; ++k) m[k] = t[k];
        }
    }

    __shared__ float s_agg[8][12];
    __shared__ float s_incl[8][12];
    if (lane == 31) {
#pragma unroll
        for (int k = 0; k < 12; ++k) s_agg[warp][k] = m[k];
    }
    __syncthreads();

    // warp 0 scans the 8 warp aggregates (all 32 lanes participate in shfls)
    if (warp == 0) {
        int src = lane < 8 ? lane : 7;
        float a[12];
#pragma unroll
        for (int k = 0; k < 12; ++k) a[k] = s_agg[src][k];
#pragma unroll
        for (int dlt = 1; dlt < 8; dlt <<= 1) {
            float o[12];
#pragma unroll
            for (int k = 0; k < 12; ++k) o[k] = __shfl_up_sync(0xffffffffu, a[k], dlt);
            if (lane >= dlt && lane < 8) {
                float t[12]; affmul(o, a, t);
#pragma unroll
                for (int k = 0; k < 12; ++k) a[k] = t[k];
            }
        }
        if (lane < 8) {
#pragma unroll
            for (int k = 0; k < 12; ++k) s_incl[lane][k] = a[k];
        }
    }
    __syncthreads();

    if (warp > 0) {
        float sd[12], t[12];
#pragma unroll
        for (int k = 0; k < 12; ++k) sd[k] = s_incl[warp - 1][k];
        affmul(sd, m, t);
#pragma unroll
        for (int k = 0; k < 12; ++k) m[k] = t[k];
    }

    // store local (block-relative) inclusive prefix, SoA for coalescing
#pragma unroll
    for (int k = 0; k < 12; ++k) g_local[k * B_CHAIN + e] = m[k];

    if (threadIdx.x == TPB - 1) {
#pragma unroll
        for (int k = 0; k < 12; ++k) g_agg[blockIdx.x * 12 + k] = m[k];
    }
}

// ---------------------------------------------------------------------------
// K2: single block scans the 64 block aggregates -> exclusive seeds.
// ---------------------------------------------------------------------------
__global__ void k_scan2()
{
    const int t    = threadIdx.x;       // 0..63
    const int lane = t & 31;
    const int w    = t >> 5;

    float a[12];
#pragma unroll
    for (int k = 0; k < 12; ++k) a[k] = g_agg[t * 12 + k];

#pragma unroll
    for (int dlt = 1; dlt < 32; dlt <<= 1) {
        float o[12];
#pragma unroll
        for (int k = 0; k < 12; ++k) o[k] = __shfl_up_sync(0xffffffffu, a[k], dlt);
        if (lane >= dlt) {
            float tm[12]; affmul(o, a, tm);
#pragma unroll
            for (int k = 0; k < 12; ++k) a[k] = tm[k];
        }
    }

    __shared__ float s_tot[12];
    __shared__ float s_incl[64][12];
    if (t == 31) {
#pragma unroll
        for (int k = 0; k < 12; ++k) s_tot[k] = a[k];
    }
    __syncthreads();
    if (w == 1) {
        float tm[12]; affmul(s_tot, a, tm);
#pragma unroll
        for (int k = 0; k < 12; ++k) a[k] = tm[k];
    }
#pragma unroll
    for (int k = 0; k < 12; ++k) s_incl[t][k] = a[k];
    __syncthreads();

    float sd[12];
    if (t == 0) {
        sd[0]=1.f; sd[1]=0.f; sd[2]=0.f;  sd[3]=0.f;
        sd[4]=0.f; sd[5]=1.f; sd[6]=0.f;  sd[7]=0.f;
        sd[8]=0.f; sd[9]=0.f; sd[10]=1.f; sd[11]=0.f;
    } else {
#pragma unroll
        for (int k = 0; k < 12; ++k) sd[k] = s_incl[t - 1][k];
    }
#pragma unroll
    for (int k = 0; k < 12; ++k) g_seed[t * 12 + k] = sd[k];
}

// ---------------------------------------------------------------------------
// K3: one thread per side chain. Rebuild parent's global transform
// (seed @ local), emit the backbone coord, then walk 15 bond steps.
// ---------------------------------------------------------------------------
__global__ void __launch_bounds__(TPB)
k_chains(const float* __restrict__ dofs,
         const int*   __restrict__ gen1_parents,
         const int*   __restrict__ kin_id,
         float*       __restrict__ out)
{
    const int c = blockIdx.x * TPB + threadIdx.x;   // chain id 0..16383

    const int parent = gen1_parents[c];             // = c + 1
    const int e      = parent - 1;
    const int b      = e >> 8;                      // K1 block index (TPB=256)

    float loc[12], sd[12], M[12];
#pragma unroll
    for (int k = 0; k < 12; ++k) loc[k] = g_local[k * B_CHAIN + e];
#pragma unroll
    for (int k = 0; k < 12; ++k) sd[k] = g_seed[b * 12 + k];
    affmul(sd, loc, M);

    // backbone coordinate for this parent atom (covers all atoms 1..16384)
    {
        int kid = kin_id[parent];
        out[kid * 3 + 0] = M[3];
        out[kid * 3 + 1] = M[7];
        out[kid * 3 + 2] = M[11];
    }

    // side chain: atoms are contiguous, all doftype==2 (bond)
    const int atom0 = 1 + B_CHAIN + c * S_SIDE;
#pragma unroll
    for (int s = 0; s < S_SIDE; ++s) {
        const int atom = atom0 + s;
        float4 d = reinterpret_cast<const float4*>(dofs)[atom - 1];
        float h[12], t[12];
        bond_ht(d.x, d.y, d.z, d.w, h);
        affmul(M, h, t);
#pragma unroll
        for (int k = 0; k < 12; ++k) M[k] = t[k];
        int kid = kin_id[atom];
        out[kid * 3 + 0] = M[3];
        out[kid * 3 + 1] = M[7];
        out[kid * 3 + 2] = M[11];
    }
}

extern "C" void kernel_launch(void* const* d_in, const int* in_sizes, int n_in,
                              void* d_out, int out_size)
{
    const float* dofs         = (const float*)d_in[0];
    const int*   doftype      = (const int*)  d_in[4];
    const int*   gen1_parents = (const int*)  d_in[7];
    const int*   kin_id       = (const int*)  d_in[8];
    float*       out          = (float*)d_out;

    k_scan1<<<NBLK, TPB>>>(dofs, doftype);
    k_scan2<<<1, 64>>>();
    k_chains<<<NBLK, TPB>>>(dofs, gen1_parents, kin_id, out);
}

// round 2
// speedup vs baseline: 1.2429x; 1.2429x over previous
#include <cuda_runtime.h>

// KinematicDOFs: backbone prefix-product of 16384 affine transforms +
// 16384 independent 15-long side chains, output = scattered translations.
//
// R2: side chains parallelized 16-lanes-per-chain (segmented shfl scan,
// depth 4 instead of 15 serial steps); backbone scan spread over 128 blocks.

#define B_CHAIN 16384
#define S_SIDE  15

#define TPB1    128
#define NBLK1   (B_CHAIN / TPB1)     // 128
#define LOG_TPB1_SHIFT 7             // e >> 7 -> block index

#define TPB3    256
#define NBLK3   ((B_CHAIN * 16) / TPB3)  // 1024

// scratch (no cudaMalloc allowed)
__device__ float g_local[12 * B_CHAIN];   // SoA: component k at g_local[k*B_CHAIN + e]
__device__ float g_agg[NBLK1 * 12];       // per-block inclusive totals
__device__ float g_seed[NBLK1 * 12];      // exclusive prefix of block totals

// c = a @ b for affine 3x4 (row-major, col 3 = translation)
__device__ __forceinline__ void affmul(const float* a, const float* b, float* c)
{
#pragma unroll
    for (int i = 0; i < 3; ++i) {
        float a0 = a[i*4+0], a1 = a[i*4+1], a2 = a[i*4+2], a3 = a[i*4+3];
        c[i*4+0] = a0*b[0] + a1*b[4] + a2*b[8];
        c[i*4+1] = a0*b[1] + a1*b[5] + a2*b[9];
        c[i*4+2] = a0*b[2] + a1*b[6] + a2*b[10];
        c[i*4+3] = a0*b[3] + a1*b[7] + a2*b[11] + a3;
    }
}

// ht_bond = Rx(a) @ Rz(b) @ T(d,0,0) @ Rx(c)   (closed form)
__device__ __forceinline__ void bond_ht(float a, float b, float d, float c, float* m)
{
    float sa, ca, sb, cb, sc, cc;
    sincosf(a, &sa, &ca);
    sincosf(b, &sb, &cb);
    sincosf(c, &sc, &cc);
    m[0] = cb;      m[1] = -sb*cc;            m[2] =  sb*sc;            m[3]  = d*cb;
    m[4] = ca*sb;   m[5] = ca*cb*cc - sa*sc;  m[6] = -ca*cb*sc - sa*cc; m[7] = ca*d*sb;
    m[8] = sa*sb;   m[9] = sa*cb*cc + ca*sc;  m[10]= -sa*cb*sc + ca*cc; m[11]= sa*d*sb;
}

__device__ __forceinline__ void make_ht(int dt, float4 d, float* m)
{
    if (dt == 2) {
        bond_ht(d.x, d.y, d.z, d.w, m);
    } else if (dt == 1) {
        // jump with f4=f5=0 (only dof_idx 0..3 ever set): T(f0,f1,f2) @ Rx(f3)
        float s3, c3; sincosf(d.w, &s3, &c3);
        m[0]=1.f; m[1]=0.f; m[2]=0.f;  m[3]=d.x;
        m[4]=0.f; m[5]=c3;  m[6]=-s3;  m[7]=d.y;
        m[8]=0.f; m[9]=s3;  m[10]=c3;  m[11]=d.z;
    } else {
        m[0]=1.f; m[1]=0.f; m[2]=0.f;  m[3]=0.f;
        m[4]=0.f; m[5]=1.f; m[6]=0.f;  m[7]=0.f;
        m[8]=0.f; m[9]=0.f; m[10]=1.f; m[11]=0.f;
    }
}

// ---------------------------------------------------------------------------
// K1: per-block inclusive scan of backbone elements (atoms 1..16384).
// 128 blocks x 128 threads -> all SMs covered.
// ---------------------------------------------------------------------------
__global__ void __launch_bounds__(TPB1)
k_scan1(const float* __restrict__ dofs, const int* __restrict__ doftype)
{
    const int e    = blockIdx.x * TPB1 + threadIdx.x;  // 0..16383, atom = e+1
    const int atom = e + 1;
    const int lane = threadIdx.x & 31;
    const int warp = threadIdx.x >> 5;                 // 0..3

    float4 d = reinterpret_cast<const float4*>(dofs)[e];
    float m[12];
    make_ht(doftype[atom], d, m);

    // warp inclusive scan (Hillis-Steele)
#pragma unroll
    for (int dlt = 1; dlt < 32; dlt <<= 1) {
        float o[12];
#pragma unroll
        for (int k = 0; k < 12; ++k) o[k] = __shfl_up_sync(0xffffffffu, m[k], dlt);
        if (lane >= dlt) {
            float t[12]; affmul(o, m, t);
#pragma unroll
            for (int k = 0; k < 12; ++k) m[k] = t[k];
        }
    }

    __shared__ float s_agg[4][12];
    __shared__ float s_incl[4][12];
    if (lane == 31) {
#pragma unroll
        for (int k = 0; k < 12; ++k) s_agg[warp][k] = m[k];
    }
    __syncthreads();

    // warp 0 scans the 4 warp aggregates
    if (warp == 0) {
        int src = lane < 4 ? lane : 3;
        float a[12];
#pragma unroll
        for (int k = 0; k < 12; ++k) a[k] = s_agg[src][k];
#pragma unroll
        for (int dlt = 1; dlt < 4; dlt <<= 1) {
            float o[12];
#pragma unroll
            for (int k = 0; k < 12; ++k) o[k] = __shfl_up_sync(0xffffffffu, a[k], dlt);
            if (lane >= dlt && lane < 4) {
                float t[12]; affmul(o, a, t);
#pragma unroll
                for (int k = 0; k < 12; ++k) a[k] = t[k];
            }
        }
        if (lane < 4) {
#pragma unroll
            for (int k = 0; k < 12; ++k) s_incl[lane][k] = a[k];
        }
    }
    __syncthreads();

    if (warp > 0) {
        float sd[12], t[12];
#pragma unroll
        for (int k = 0; k < 12; ++k) sd[k] = s_incl[warp - 1][k];
        affmul(sd, m, t);
#pragma unroll
        for (int k = 0; k < 12; ++k) m[k] = t[k];
    }

    // store local (block-relative) inclusive prefix, SoA for coalescing
#pragma unroll
    for (int k = 0; k < 12; ++k) g_local[k * B_CHAIN + e] = m[k];

    if (threadIdx.x == TPB1 - 1) {
#pragma unroll
        for (int k = 0; k < 12; ++k) g_agg[blockIdx.x * 12 + k] = m[k];
    }
}

// ---------------------------------------------------------------------------
// K2: single block (128 threads) scans the 128 block aggregates -> seeds.
// ---------------------------------------------------------------------------
__global__ void __launch_bounds__(128)
k_scan2()
{
    const int t    = threadIdx.x;       // 0..127
    const int lane = t & 31;
    const int w    = t >> 5;            // 0..3

    float a[12];
#pragma unroll
    for (int k = 0; k < 12; ++k) a[k] = g_agg[t * 12 + k];

#pragma unroll
    for (int dlt = 1; dlt < 32; dlt <<= 1) {
        float o[12];
#pragma unroll
        for (int k = 0; k < 12; ++k) o[k] = __shfl_up_sync(0xffffffffu, a[k], dlt);
        if (lane >= dlt) {
            float tm[12]; affmul(o, a, tm);
#pragma unroll
            for (int k = 0; k < 12; ++k) a[k] = tm[k];
        }
    }

    __shared__ float s_wagg[4][12];
    __shared__ float s_wincl[4][12];
    __shared__ float s_incl[128][12];
    if (lane == 31) {
#pragma unroll
        for (int k = 0; k < 12; ++k) s_wagg[w][k] = a[k];
    }
    __syncthreads();

    if (w == 0) {
        int src = lane < 4 ? lane : 3;
        float b[12];
#pragma unroll
        for (int k = 0; k < 12; ++k) b[k] = s_wagg[src][k];
#pragma unroll
        for (int dlt = 1; dlt < 4; dlt <<= 1) {
            float o[12];
#pragma unroll
            for (int k = 0; k < 12; ++k) o[k] = __shfl_up_sync(0xffffffffu, b[k], dlt);
            if (lane >= dlt && lane < 4) {
                float tm[12]; affmul(o, b, tm);
#pragma unroll
                for (int k = 0; k < 12; ++k) b[k] = tm[k];
            }
        }
        if (lane < 4) {
#pragma unroll
            for (int k = 0; k < 12; ++k) s_wincl[lane][k] = b[k];
        }
    }
    __syncthreads();

    if (w > 0) {
        float sd[12], tm[12];
#pragma unroll
        for (int k = 0; k < 12; ++k) sd[k] = s_wincl[w - 1][k];
        affmul(sd, a, tm);
#pragma unroll
        for (int k = 0; k < 12; ++k) a[k] = tm[k];
    }
#pragma unroll
    for (int k = 0; k < 12; ++k) s_incl[t][k] = a[k];
    __syncthreads();

    float sd[12];
    if (t == 0) {
        sd[0]=1.f; sd[1]=0.f; sd[2]=0.f;  sd[3]=0.f;
        sd[4]=0.f; sd[5]=1.f; sd[6]=0.f;  sd[7]=0.f;
        sd[8]=0.f; sd[9]=0.f; sd[10]=1.f; sd[11]=0.f;
    } else {
#pragma unroll
        for (int k = 0; k < 12; ++k) sd[k] = s_incl[t - 1][k];
    }
#pragma unroll
    for (int k = 0; k < 12; ++k) g_seed[t * 12 + k] = sd[k];
}

// ---------------------------------------------------------------------------
// K3: 16 lanes per chain. Lane 0 = parent global transform (seed @ local),
// lanes 1..15 = one bond_ht each; segmented inclusive scan over the 16
// lanes gives every atom's global transform in 4 shfl rounds.
// ---------------------------------------------------------------------------
__global__ void __launch_bounds__(TPB3)
k_chains(const float* __restrict__ dofs,
         const int*   __restrict__ kin_id,
         float*       __restrict__ out)
{
    const int tid   = blockIdx.x * TPB3 + threadIdx.x;
    const int chain = tid >> 4;          // 0..16383
    const int r     = tid & 15;          // lane within chain

    float M[12];
    int atom;
    if (r == 0) {
        // parent = chain+1 (gen1_parents is identity 1..16384)
        atom = chain + 1;
        const int e = chain;
        const int b = e >> LOG_TPB1_SHIFT;
        float loc[12], sd[12];
#pragma unroll
        for (int k = 0; k < 12; ++k) loc[k] = g_local[k * B_CHAIN + e];
#pragma unroll
        for (int k = 0; k < 12; ++k) sd[k] = g_seed[b * 12 + k];
        affmul(sd, loc, M);
    } else {
        atom = 1 + B_CHAIN + chain * S_SIDE + (r - 1);
        float4 d = reinterpret_cast<const float4*>(dofs)[atom - 1];
        bond_ht(d.x, d.y, d.z, d.w, M);
    }

    // segmented inclusive scan over 16 lanes (half-warp = one chain)
#pragma unroll
    for (int dlt = 1; dlt < 16; dlt <<= 1) {
        float o[12];
#pragma unroll
        for (int k = 0; k < 12; ++k) o[k] = __shfl_up_sync(0xffffffffu, M[k], dlt);
        if (r >= dlt) {
            float t[12]; affmul(o, M, t);
#pragma unroll
            for (int k = 0; k < 12; ++k) M[k] = t[k];
        }
    }

    const int kid = kin_id[atom];
    out[kid * 3 + 0] = M[3];
    out[kid * 3 + 1] = M[7];
    out[kid * 3 + 2] = M[11];
}

extern "C" void kernel_launch(void* const* d_in, const int* in_sizes, int n_in,
                              void* d_out, int out_size)
{
    const float* dofs    = (const float*)d_in[0];
    const int*   doftype = (const int*)  d_in[4];
    const int*   kin_id  = (const int*)  d_in[8];
    float*       out     = (float*)d_out;

    k_scan1<<<NBLK1, TPB1>>>(dofs, doftype);
    k_scan2<<<1, 128>>>();
    k_chains<<<NBLK3, TPB3>>>(dofs, kin_id, out);
}